// round 14
// baseline (speedup 1.0000x reference)
#include <cuda_runtime.h>
#include <cstdint>
#include <cstddef>

#define N_SP 4096
#define HB 4
#define LOG2E 1.4426950408889634f

typedef unsigned long long ull;

// ---------------- packed f32x2 / misc helpers ----------------
__device__ __forceinline__ void ffma2(ull &d, ull a, ull b){
    asm("fma.rn.f32x2 %0, %1, %2, %0;" : "+l"(d) : "l"(a), "l"(b));
}
__device__ __forceinline__ void unpack2(ull v, float &lo, float &hi){
    asm("mov.b64 {%0, %1}, %2;" : "=f"(lo), "=f"(hi) : "l"(v));
}
__device__ __forceinline__ ull dup2(float x){
    ull r; asm("mov.b64 %0, {%1, %1};" : "=l"(r) : "f"(x)); return r;
}
__device__ __forceinline__ float fexp2(float x){
    float y; asm("ex2.approx.f32 %0, %1;" : "=f"(y) : "f"(x)); return y;
}
__device__ __forceinline__ uint32_t smaddr(const void* p){
    return (uint32_t)__cvta_generic_to_shared(p);
}
#define CPASYNC16(dst, src) \
    asm volatile("cp.async.cg.shared.global [%0], [%1], 16;" :: "r"(dst), "l"(src) : "memory")
#define CPASYNC_COMMIT() asm volatile("cp.async.commit_group;" ::: "memory")
#define CPASYNC_WAIT0()  asm volatile("cp.async.wait_group 0;" ::: "memory")

// ---------------- scratch (device globals; allocation is forbidden) ----------------
__device__ __align__(128) float g_x2u[HB*256*N_SP];
__device__ __align__(128) float g_x1u[HB*512*N_SP];
__device__ __align__(128) float g_q[HB*(64+32+16)*N_SP];
__device__ __align__(128) float g_k[HB*(64+32+16)*N_SP];
__device__ __align__(128) float g_s[3*HB*N_SP];
__device__ __align__(128) float g_a[3*HB*N_SP];
__device__ __align__(128) float g_u[3*512];
__device__ __align__(128) float g_sb[3];

#define Q_OFF0 0
#define Q_OFF1 (HB*64*N_SP)
#define Q_OFF2 (HB*(64+32)*N_SP)

// ---------------- bilinear upsample body (align_corners=True) to 64x64 ----------------
__device__ __forceinline__ void upsample_body(int bid, int tid,
                                              const float* __restrict__ in,
                                              float* __restrict__ out,
                                              int planes, int isz)
{
    int idx = bid * 256 + tid;
    if (idx >= planes * N_SP) return;
    int ox = idx & 63, oy = (idx >> 6) & 63, p = idx >> 12;
    float r = (float)(isz - 1) / 63.0f;
    float cy = oy * r, cx = ox * r;
    int iy = (int)cy; if (iy > isz - 2) iy = isz - 2;
    int ix = (int)cx; if (ix > isz - 2) ix = isz - 2;
    float wy = cy - (float)iy, wx = cx - (float)ix;
    const float* base = in + (size_t)p * isz * isz;
    float v00 = base[iy*isz + ix],     v01 = base[iy*isz + ix + 1];
    float v10 = base[(iy+1)*isz + ix], v11 = base[(iy+1)*isz + ix + 1];
    float top = v00 + wx * (v01 - v00);
    float bot = v10 + wx * (v11 - v10);
    out[idx] = top + wy * (bot - top);
}

// ---------------- u = wa @ Wv, sb = wa . bv ----------------
__device__ __forceinline__ void u_body(int ub, int tid,
    const float* __restrict__ wa, const float* __restrict__ Wv,
    const float* __restrict__ bv, float* __restrict__ u, float* __restrict__ sb, int C)
{
    __shared__ float red[4][64];
    int c2i = tid & 63;
    int cg  = tid >> 6;
    int c2  = ub * 64 + c2i;
    float acc = 0.f;
    #pragma unroll 8
    for (int c = cg; c < C; c += 4)
        acc += __ldg(&wa[c]) * Wv[c*C + c2];
    red[cg][c2i] = acc;
    __syncthreads();
    if (tid < 64)
        u[ub*64 + tid] = red[0][tid] + red[1][tid] + red[2][tid] + red[3][tid];
    if (ub == 0 && tid >= 192 && tid < 224){
        int l = tid - 192;
        float a = 0.f;
        for (int c = l; c < C; c += 32) a += wa[c] * bv[c];
        #pragma unroll
        for (int o = 16; o; o >>= 1) a += __shfl_down_sync(0xffffffffu, a, o);
        if (l == 0) *sb = a;
    }
}

// ---------------- merged pre kernel: 3x u + both upsamples ----------------
__global__ __launch_bounds__(256) void pre_all(
    const float* __restrict__ wa0, const float* __restrict__ Wv0, const float* __restrict__ bv0,
    const float* __restrict__ wa1, const float* __restrict__ Wv1, const float* __restrict__ bv1,
    const float* __restrict__ wa2, const float* __restrict__ Wv2, const float* __restrict__ bv2,
    const float* __restrict__ x1, const float* __restrict__ x2)
{
    int bx = blockIdx.x, tid = threadIdx.x;
    if (bx < 8)       u_body(bx,    tid, wa0, Wv0, bv0, g_u,        g_sb,     512);
    else if (bx < 12) u_body(bx-8,  tid, wa1, Wv1, bv1, g_u + 512,  g_sb + 1, 256);
    else if (bx < 14) u_body(bx-12, tid, wa2, Wv2, bv2, g_u + 1024, g_sb + 2, 128);
    else if (bx < 14 + (HB*512*N_SP)/256)
        upsample_body(bx - 14, tid, x1, g_x1u, HB*512, 16);
    else
        upsample_body(bx - 14 - (HB*512*N_SP)/256, tid, x2, g_x2u, HB*256, 32);
}

// ---------------- merged s kernel: s[b,m] = u . x[:,m] + sb ----------------
__device__ __forceinline__ void s_body(const float* __restrict__ X,
                                       const float* __restrict__ u,
                                       const float* __restrict__ sb,
                                       float* __restrict__ sout, int C,
                                       int b, int n)
{
    const float* Xb = X + (size_t)b * C * N_SP + n;
    float acc = 0.f;
    #pragma unroll 8
    for (int c = 0; c < C; c++) acc += __ldg(&u[c]) * Xb[(size_t)c * N_SP];
    sout[b*N_SP + n] = acc + sb[0];
}

__global__ void s_all(const float* __restrict__ x3)
{
    int b = blockIdx.y, z = blockIdx.z;
    int n = blockIdx.x * 256 + threadIdx.x;
    if (z == 0)      s_body(g_x1u, g_u,        g_sb,     g_s,             512, b, n);
    else if (z == 1) s_body(g_x2u, g_u + 512,  g_sb + 1, g_s + HB*N_SP,   256, b, n);
    else             s_body(x3,    g_u + 1024, g_sb + 2, g_s + 2*HB*N_SP, 128, b, n);
}

// ---------------- q/k projection body (f32x2 tiled GEMM); q pre-scaled by log2e ------
template<int C, int D>
__device__ __forceinline__ void qkprep_body(
    float* __restrict__ smbuf,
    const float* __restrict__ X,
    const float* __restrict__ Wq, const float* __restrict__ bq,
    const float* __restrict__ Wk, const float* __restrict__ bk,
    float* __restrict__ qg, float* __restrict__ kg,
    int xb, int b)
{
    constexpr int ROWS = 2*D;          // 128 / 64 / 32
    constexpr int RGn  = ROWS/4;       // 32 / 16 / 8
    constexpr int NG   = 256/RGn;      // 8 / 16 / 32
    constexpr int BN   = NG*8;         // 64 / 128 / 256
    constexpr int WCG  = NG/8;         // 1 / 2 / 4
    constexpr int WDS  = 2*ROWS + 4;   // padded dup-w stride
    float* Xs = smbuf;                 // 16*BN
    float* Wd = smbuf + 16*BN;         // 16*WDS
    int tid = threadIdx.x;
    int lane = tid & 31, wid = tid >> 5;
    int cg = (lane & 7) + 8*(wid % WCG);
    int rg = (lane >> 3) + 4*(wid / WCG);
    int n0 = xb * BN;
    const float* Xb = X + (size_t)b * C * N_SP;

    ull acc[4][4];
    #pragma unroll
    for (int r = 0; r < 4; r++)
        #pragma unroll
        for (int p = 0; p < 4; p++) acc[r][p] = 0ull;

    for (int c0 = 0; c0 < C; c0 += 16){
        __syncthreads();
        #pragma unroll
        for (int i = 0; i < BN/16; i++){
            int idx = tid + i*256;
            int cc = idx / BN, n = idx % BN;
            Xs[cc*BN + n] = Xb[(size_t)(c0+cc)*N_SP + n0 + n];
        }
        #pragma unroll
        for (int i = 0; i < ROWS/16; i++){
            int idx = tid + i*256;
            int cc = idx & 15, r = idx >> 4;
            float w = (r < D) ? Wq[r*C + c0 + cc] : Wk[(r-D)*C + c0 + cc];
            *(float2*)&Wd[cc*WDS + 2*r] = make_float2(w, w);
        }
        __syncthreads();
        #pragma unroll
        for (int cc = 0; cc < 16; cc++){
            const ulonglong2* xp = (const ulonglong2*)(Xs + cc*BN + cg*8);
            ulonglong2 xa = xp[0], xb2 = xp[1];
            const ulonglong2* wp = (const ulonglong2*)(Wd + cc*WDS + rg*8);
            ulonglong2 wa = wp[0], wb = wp[1];
            ull xv0 = xa.x, xv1 = xa.y, xv2 = xb2.x, xv3 = xb2.y;
            ffma2(acc[0][0], wa.x, xv0); ffma2(acc[0][1], wa.x, xv1);
            ffma2(acc[0][2], wa.x, xv2); ffma2(acc[0][3], wa.x, xv3);
            ffma2(acc[1][0], wa.y, xv0); ffma2(acc[1][1], wa.y, xv1);
            ffma2(acc[1][2], wa.y, xv2); ffma2(acc[1][3], wa.y, xv3);
            ffma2(acc[2][0], wb.x, xv0); ffma2(acc[2][1], wb.x, xv1);
            ffma2(acc[2][2], wb.x, xv2); ffma2(acc[2][3], wb.x, xv3);
            ffma2(acc[3][0], wb.y, xv0); ffma2(acc[3][1], wb.y, xv1);
            ffma2(acc[3][2], wb.y, xv2); ffma2(acc[3][3], wb.y, xv3);
        }
    }
    #pragma unroll
    for (int r = 0; r < 4; r++){
        int row = rg*4 + r;
        #pragma unroll
        for (int p = 0; p < 4; p++){
            float lo, hi; unpack2(acc[r][p], lo, hi);
            int n = n0 + cg*8 + 2*p;
            if (row < D){
                float bqr = __ldg(&bq[row]);
                *(float2*)&qg[((size_t)b*D + row)*N_SP + n] =
                    make_float2((lo + bqr)*LOG2E, (hi + bqr)*LOG2E);
            } else {
                int rr = row - D;
                float bkr = __ldg(&bk[rr]);
                *(float2*)&kg[((size_t)b*D + rr)*N_SP + n] =
                    make_float2(lo + bkr, hi + bkr);
            }
        }
    }
}

// merged qkprep: grid (112, HB). x<64: scale0; x<96: scale1; else scale2.
__global__ __launch_bounds__(256) void qkprep_all(
    const float* __restrict__ x3,
    const float* __restrict__ Wq0, const float* __restrict__ bq0,
    const float* __restrict__ Wk0, const float* __restrict__ bk0,
    const float* __restrict__ Wq1, const float* __restrict__ bq1,
    const float* __restrict__ Wk1, const float* __restrict__ bk1,
    const float* __restrict__ Wq2, const float* __restrict__ bq2,
    const float* __restrict__ Wk2, const float* __restrict__ bk2)
{
    __shared__ __align__(16) float buf[5184];
    int x = blockIdx.x, b = blockIdx.y;
    if (x < 64)
        qkprep_body<512,64>(buf, g_x1u, Wq0, bq0, Wk0, bk0,
                            g_q + Q_OFF0, g_k + Q_OFF0, x, b);
    else if (x < 96)
        qkprep_body<256,32>(buf, g_x2u, Wq1, bq1, Wk1, bk1,
                            g_q + Q_OFF1, g_k + Q_OFF1, x - 64, b);
    else
        qkprep_body<128,16>(buf, x3, Wq2, bq2, Wk2, bk2,
                            g_q + Q_OFF2, g_k + Q_OFF2, x - 96, b);
}

// ---------------- barrier-free streaming attention (v4) ----------------
// a[n] = ba + sum_m 2^l[n,m] s[m] / sum_m 2^l[n,m]  (|l|<~90<127: no overflow).
// Per-warp SINGLE-buffered k slices via cp.async (next tile issued before the exp
// epilogue, so the epilogue overlaps the load); s double-buffered (epilogue reads it).
// 2-way split accumulators; no block barriers in the mainloop. 3 CTAs/SM.
template<int D>
__device__ __forceinline__ void attn_body(
    const float* __restrict__ qg, const float* __restrict__ kg,
    const float* __restrict__ sg, const float* __restrict__ bap,
    float* __restrict__ aout, int nblk, int b)
{
    extern __shared__ float sm[];
    float* smq = sm;                    // D*64
    float* smk = sm + D*64;             // 8 warps * D*16 (single buffer)
    float* sms = sm + D*64 + 128*D;     // 8 * 2 * 16 (double)
    float* smr = sms + 256;             // 8*64*2
    int tid = threadIdx.x;
    int lane = tid & 31, w = tid >> 5;
    int n0 = nblk * 64;
    const float* qb = qg + (size_t)b * D * N_SP;
    const float* kb = kg + (size_t)b * D * N_SP;
    const float* sb = sg + (size_t)b * N_SP;

    #pragma unroll
    for (int i = 0; i < (D*64)/256; i++){
        int idx = tid + i*256;
        int kk = idx >> 6, n = idx & 63;
        smq[kk*64 + n] = qb[(size_t)kk*N_SP + n0 + n];
    }
    __syncthreads();

    float* myk = smk + w*(D*16);
    float* mys = sms + w*32;
    int m0 = w*16;                       // warp's m-offset within each 128-m tile
    int kko = lane >> 2, ch = (lane & 3)*4;

    // prefetch tile 0 (per warp)
    #pragma unroll
    for (int i = 0; i < D/8; i++){
        int kk = i*8 + kko;
        CPASYNC16(smaddr(&myk[kk*16 + ch]), &kb[(size_t)kk*N_SP + m0 + ch]);
    }
    if (lane < 4)
        CPASYNC16(smaddr(&mys[lane*4]), &sb[m0 + lane*4]);
    CPASYNC_COMMIT();
    CPASYNC_WAIT0();
    __syncwarp();

    float den0a = 0.f, den0b = 0.f, num0a = 0.f, num0b = 0.f;
    float den1a = 0.f, den1b = 0.f, num1a = 0.f, num1b = 0.f;

    for (int mt = 0; mt < 32; mt++){
        int cur = mt & 1;

        ull acc[16];
        #pragma unroll
        for (int j = 0; j < 16; j++) acc[j] = 0ull;

        #pragma unroll 8
        for (int kk = 0; kk < D; kk++){
            ull qv = *(const ull*)&smq[kk*64 + 2*lane];
            float qlo, qhi; unpack2(qv, qlo, qhi);
            ull qx = dup2(qlo), qy = dup2(qhi);
            const ulonglong2* kr = (const ulonglong2*)(myk + kk*16);
            ulonglong2 k0 = kr[0], k1 = kr[1], k2 = kr[2], k3 = kr[3];
            ffma2(acc[0],  qx, k0.x); ffma2(acc[1],  qx, k0.y);
            ffma2(acc[2],  qx, k1.x); ffma2(acc[3],  qx, k1.y);
            ffma2(acc[4],  qx, k2.x); ffma2(acc[5],  qx, k2.y);
            ffma2(acc[6],  qx, k3.x); ffma2(acc[7],  qx, k3.y);
            ffma2(acc[8],  qy, k0.x); ffma2(acc[9],  qy, k0.y);
            ffma2(acc[10], qy, k1.x); ffma2(acc[11], qy, k1.y);
            ffma2(acc[12], qy, k2.x); ffma2(acc[13], qy, k2.y);
            ffma2(acc[14], qy, k3.x); ffma2(acc[15], qy, k3.y);
        }

        // issue next tile's loads NOW (k buffer fully consumed into acc; the exp
        // epilogue below overlaps the global-load latency). s goes to the other buf.
        if (mt < 31){
            int mg = (mt+1)*128 + m0;
            #pragma unroll
            for (int i = 0; i < D/8; i++){
                int kk = i*8 + kko;
                CPASYNC16(smaddr(&myk[kk*16 + ch]), &kb[(size_t)kk*N_SP + mg + ch]);
            }
            if (lane < 4)
                CPASYNC16(smaddr(&mys[(cur^1)*16 + lane*4]), &sb[mg + lane*4]);
            CPASYNC_COMMIT();
        }

        // epilogue: inline unpack -> exp -> 2-way split accumulate; sv shared by rows
        #pragma unroll
        for (int jj = 0; jj < 4; jj++){
            float4 s4 = *(const float4*)&mys[cur*16 + 4*jj];
            float l0, l1, l2, l3;
            unpack2(acc[2*jj],   l0, l1);
            unpack2(acc[2*jj+1], l2, l3);
            float e0 = fexp2(l0), e1 = fexp2(l1), e2 = fexp2(l2), e3 = fexp2(l3);
            den0a += e0; den0b += e1;
            num0a = fmaf(e0, s4.x, num0a); num0b = fmaf(e1, s4.y, num0b);
            den0a += e2; den0b += e3;
            num0a = fmaf(e2, s4.z, num0a); num0b = fmaf(e3, s4.w, num0b);

            unpack2(acc[8+2*jj],   l0, l1);
            unpack2(acc[8+2*jj+1], l2, l3);
            e0 = fexp2(l0); e1 = fexp2(l1); e2 = fexp2(l2); e3 = fexp2(l3);
            den1a += e0; den1b += e1;
            num1a = fmaf(e0, s4.x, num1a); num1b = fmaf(e1, s4.y, num1b);
            den1a += e2; den1b += e3;
            num1a = fmaf(e2, s4.z, num1a); num1b = fmaf(e3, s4.w, num1b);
        }

        if (mt < 31){
            CPASYNC_WAIT0();
            __syncwarp();
        }
    }

    {
        int r0 = lane*2;
        float* p0 = &smr[(w*64 + r0)*2];
        p0[0] = den0a + den0b; p0[1] = num0a + num0b;
        float* p1 = &smr[(w*64 + r0 + 1)*2];
        p1[0] = den1a + den1b; p1[1] = num1a + num1b;
    }
    __syncthreads();
    if (tid < 64){
        float dsum = 0.f, nsum = 0.f;
        #pragma unroll
        for (int i = 0; i < 8; i++){
            dsum += smr[(i*64 + tid)*2];
            nsum += smr[(i*64 + tid)*2 + 1];
        }
        aout[(size_t)b*N_SP + n0 + tid] = bap[0] + nsum / dsum;
    }
}

// merged attention: grid.x = 768 (scale0 first for wave balance), 3 CTAs/SM
__global__ __launch_bounds__(256, 3) void attn_all(
    const float* __restrict__ ba0, const float* __restrict__ ba1,
    const float* __restrict__ ba2)
{
    int x = blockIdx.x;
    if (x < 256)
        attn_body<64>(g_q + Q_OFF0, g_k + Q_OFF0, g_s, ba0, g_a, x & 63, x >> 6);
    else if (x < 512){
        int y = x - 256;
        attn_body<32>(g_q + Q_OFF1, g_k + Q_OFF1, g_s + HB*N_SP, ba1,
                      g_a + HB*N_SP, y & 63, y >> 6);
    } else {
        int y = x - 512;
        attn_body<16>(g_q + Q_OFF2, g_k + Q_OFF2, g_s + 2*HB*N_SP, ba2,
                      g_a + 2*HB*N_SP, y & 63, y >> 6);
    }
}

// ---------------- final fused conv: out = w2 . relu(prod * (W1 . xcat) + b1) + b2 ----
__global__ __launch_bounds__(256) void final_kernel(
    const float* __restrict__ x3, const float* __restrict__ w1,
    const float* __restrict__ b1, const float* __restrict__ w2,
    const float* __restrict__ b2, float* __restrict__ out)
{
    __shared__ __align__(16) float Ws2[2][32*32];
    __shared__ float hred[128][33];
    int tid = threadIdx.x;
    int px = tid & 127, half = tid >> 7;
    int p = blockIdx.x * 128 + px;
    int b = p >> 12, n = p & 4095;

    ull tacc[16];
    #pragma unroll
    for (int j = 0; j < 16; j++) tacc[j] = 0ull;

    for (int i = 0; i < 14; i++){
        __syncthreads();
        #pragma unroll
        for (int k = 0; k < 4; k++){
            int idx = tid + k*256;
            int o = idx & 31, cc = idx >> 5;   // conflict-free STS
            Ws2[0][cc*32 + o] = w1[o*896 + i*32 + cc];
            Ws2[1][cc*32 + o] = w1[o*896 + 448 + i*32 + cc];
        }
        __syncthreads();
        int cbase = half*448 + i*32;
        const float* src; int cb;
        if (cbase < 128){ src = x3 + (size_t)b*128*N_SP; cb = cbase; }
        else if (cbase < 384){ src = g_x2u + (size_t)b*256*N_SP; cb = cbase - 128; }
        else { src = g_x1u + (size_t)b*512*N_SP; cb = cbase - 384; }
        const float* ws = Ws2[half];
        #pragma unroll 4
        for (int cc = 0; cc < 32; cc++){
            float x = src[(size_t)(cb+cc)*N_SP + n];
            ull xx = dup2(x);
            const ulonglong2* wp = (const ulonglong2*)(ws + cc*32);
            #pragma unroll
            for (int j = 0; j < 8; j++){
                ulonglong2 wv = wp[j];
                ffma2(tacc[2*j],   wv.x, xx);
                ffma2(tacc[2*j+1], wv.y, xx);
            }
        }
    }
    __syncthreads();
    if (half == 1){
        #pragma unroll
        for (int j = 0; j < 16; j++){
            float t0, t1; unpack2(tacc[j], t0, t1);
            hred[px][2*j] = t0; hred[px][2*j+1] = t1;
        }
    }
    __syncthreads();
    if (half == 0){
        float prod = g_a[p] * g_a[HB*N_SP + p] * g_a[2*HB*N_SP + p];
        float res = b2[0];
        #pragma unroll
        for (int j = 0; j < 16; j++){
            float t0, t1; unpack2(tacc[j], t0, t1);
            t0 += hred[px][2*j]; t1 += hred[px][2*j+1];
            int o = 2*j;
            res += w2[o]   * fmaxf(prod*t0 + b1[o],   0.f);
            res += w2[o+1] * fmaxf(prod*t1 + b1[o+1], 0.f);
        }
        out[p] = res;
    }
}

// ---------------- host launcher ----------------
// 5 launches. Our launch #4 = attn_all = global launch #6 (ncu capture target).
extern "C" void kernel_launch(void* const* d_in, const int* in_sizes, int n_in,
                              void* d_out, int out_size)
{
    const float* x3 = (const float*)d_in[0];
    const float* x2 = (const float*)d_in[1];
    const float* x1 = (const float*)d_in[2];

    // smem floats for attn: q D*64 + k 128*D (single) + s 256 + merge 1024
    // D=64 -> (4096 + 8192 + 256 + 1024)*4 = 54272 B -> 3 CTAs/SM (with 85 regs)
    const int SMEMA = (64*64 + 128*64 + 256 + 1024) * 4;
    cudaFuncSetAttribute(attn_all, cudaFuncAttributeMaxDynamicSharedMemorySize, SMEMA);

    // #1: pre (3x u + upsample x1 + upsample x2)
    pre_all<<<14 + (HB*512*N_SP)/256 + (HB*256*N_SP)/256, 256>>>(
        (const float*)d_in[9],  (const float*)d_in[7],  (const float*)d_in[8],
        (const float*)d_in[17], (const float*)d_in[15], (const float*)d_in[16],
        (const float*)d_in[25], (const float*)d_in[23], (const float*)d_in[24],
        x1, x2);

    // #2: merged s (3 scales)
    s_all<<<dim3(16, HB, 3), 256>>>(x3);

    // #3: merged q/k projections
    qkprep_all<<<dim3(112, HB), 256>>>(x3,
        (const float*)d_in[3],  (const float*)d_in[4],
        (const float*)d_in[5],  (const float*)d_in[6],
        (const float*)d_in[11], (const float*)d_in[12],
        (const float*)d_in[13], (const float*)d_in[14],
        (const float*)d_in[19], (const float*)d_in[20],
        (const float*)d_in[21], (const float*)d_in[22]);

    // #4: merged attention (capture target)
    attn_all<<<768, 256, SMEMA>>>((const float*)d_in[10], (const float*)d_in[18],
                                  (const float*)d_in[26]);

    // #5: fused final
    final_kernel<<<(HB*N_SP)/128, 256>>>(x3, (const float*)d_in[27], (const float*)d_in[28],
                                         (const float*)d_in[29], (const float*)d_in[30],
                                         (float*)d_out);
}

// round 15
// speedup vs baseline: 1.0395x; 1.0395x over previous
#include <cuda_runtime.h>
#include <cstdint>
#include <cstddef>

#define N_SP 4096
#define HB 4
#define LOG2E 1.4426950408889634f

typedef unsigned long long ull;

// ---------------- packed f32x2 / misc helpers ----------------
__device__ __forceinline__ void ffma2(ull &d, ull a, ull b){
    asm("fma.rn.f32x2 %0, %1, %2, %0;" : "+l"(d) : "l"(a), "l"(b));
}
__device__ __forceinline__ void unpack2(ull v, float &lo, float &hi){
    asm("mov.b64 {%0, %1}, %2;" : "=f"(lo), "=f"(hi) : "l"(v));
}
__device__ __forceinline__ ull dup2(float x){
    ull r; asm("mov.b64 %0, {%1, %1};" : "=l"(r) : "f"(x)); return r;
}
__device__ __forceinline__ float fexp2(float x){
    float y; asm("ex2.approx.f32 %0, %1;" : "=f"(y) : "f"(x)); return y;
}
__device__ __forceinline__ uint32_t smaddr(const void* p){
    return (uint32_t)__cvta_generic_to_shared(p);
}
#define CPASYNC16(dst, src) \
    asm volatile("cp.async.cg.shared.global [%0], [%1], 16;" :: "r"(dst), "l"(src) : "memory")
#define CPASYNC_COMMIT() asm volatile("cp.async.commit_group;" ::: "memory")
#define CPASYNC_WAIT0()  asm volatile("cp.async.wait_group 0;" ::: "memory")

// ---------------- scratch (device globals; allocation is forbidden) ----------------
__device__ __align__(128) float g_x2u[HB*256*N_SP];
__device__ __align__(128) float g_x1u[HB*512*N_SP];
__device__ __align__(128) float g_q[HB*(64+32+16)*N_SP];
__device__ __align__(128) float g_k[HB*(64+32+16)*N_SP];
__device__ __align__(128) float g_s[3*HB*N_SP];
__device__ __align__(128) float g_a[3*HB*N_SP];
__device__ __align__(128) float g_u[3*512];
__device__ __align__(128) float g_sb[3];

#define Q_OFF0 0
#define Q_OFF1 (HB*64*N_SP)
#define Q_OFF2 (HB*(64+32)*N_SP)

// ---------------- bilinear upsample body (align_corners=True) to 64x64 ----------------
__device__ __forceinline__ void upsample_body(int bid, int tid,
                                              const float* __restrict__ in,
                                              float* __restrict__ out,
                                              int planes, int isz)
{
    int idx = bid * 256 + tid;
    if (idx >= planes * N_SP) return;
    int ox = idx & 63, oy = (idx >> 6) & 63, p = idx >> 12;
    float r = (float)(isz - 1) / 63.0f;
    float cy = oy * r, cx = ox * r;
    int iy = (int)cy; if (iy > isz - 2) iy = isz - 2;
    int ix = (int)cx; if (ix > isz - 2) ix = isz - 2;
    float wy = cy - (float)iy, wx = cx - (float)ix;
    const float* base = in + (size_t)p * isz * isz;
    float v00 = base[iy*isz + ix],     v01 = base[iy*isz + ix + 1];
    float v10 = base[(iy+1)*isz + ix], v11 = base[(iy+1)*isz + ix + 1];
    float top = v00 + wx * (v01 - v00);
    float bot = v10 + wx * (v11 - v10);
    out[idx] = top + wy * (bot - top);
}

// ---------------- u = wa @ Wv, sb = wa . bv ----------------
__device__ __forceinline__ void u_body(int ub, int tid,
    const float* __restrict__ wa, const float* __restrict__ Wv,
    const float* __restrict__ bv, float* __restrict__ u, float* __restrict__ sb, int C)
{
    __shared__ float red[4][64];
    int c2i = tid & 63;
    int cg  = tid >> 6;
    int c2  = ub * 64 + c2i;
    float acc = 0.f;
    #pragma unroll 8
    for (int c = cg; c < C; c += 4)
        acc += __ldg(&wa[c]) * Wv[c*C + c2];
    red[cg][c2i] = acc;
    __syncthreads();
    if (tid < 64)
        u[ub*64 + tid] = red[0][tid] + red[1][tid] + red[2][tid] + red[3][tid];
    if (ub == 0 && tid >= 192 && tid < 224){
        int l = tid - 192;
        float a = 0.f;
        for (int c = l; c < C; c += 32) a += wa[c] * bv[c];
        #pragma unroll
        for (int o = 16; o; o >>= 1) a += __shfl_down_sync(0xffffffffu, a, o);
        if (l == 0) *sb = a;
    }
}

// ---------------- merged pre kernel: 3x u + both upsamples ----------------
__global__ __launch_bounds__(256) void pre_all(
    const float* __restrict__ wa0, const float* __restrict__ Wv0, const float* __restrict__ bv0,
    const float* __restrict__ wa1, const float* __restrict__ Wv1, const float* __restrict__ bv1,
    const float* __restrict__ wa2, const float* __restrict__ Wv2, const float* __restrict__ bv2,
    const float* __restrict__ x1, const float* __restrict__ x2)
{
    int bx = blockIdx.x, tid = threadIdx.x;
    if (bx < 8)       u_body(bx,    tid, wa0, Wv0, bv0, g_u,        g_sb,     512);
    else if (bx < 12) u_body(bx-8,  tid, wa1, Wv1, bv1, g_u + 512,  g_sb + 1, 256);
    else if (bx < 14) u_body(bx-12, tid, wa2, Wv2, bv2, g_u + 1024, g_sb + 2, 128);
    else if (bx < 14 + (HB*512*N_SP)/256)
        upsample_body(bx - 14, tid, x1, g_x1u, HB*512, 16);
    else
        upsample_body(bx - 14 - (HB*512*N_SP)/256, tid, x2, g_x2u, HB*256, 32);
}

// ---------------- merged s kernel: s[b,m] = u . x[:,m] + sb ----------------
__device__ __forceinline__ void s_body(const float* __restrict__ X,
                                       const float* __restrict__ u,
                                       const float* __restrict__ sb,
                                       float* __restrict__ sout, int C,
                                       int b, int n)
{
    const float* Xb = X + (size_t)b * C * N_SP + n;
    float acc = 0.f;
    #pragma unroll 8
    for (int c = 0; c < C; c++) acc += __ldg(&u[c]) * Xb[(size_t)c * N_SP];
    sout[b*N_SP + n] = acc + sb[0];
}

__global__ void s_all(const float* __restrict__ x3)
{
    int b = blockIdx.y, z = blockIdx.z;
    int n = blockIdx.x * 256 + threadIdx.x;
    if (z == 0)      s_body(g_x1u, g_u,        g_sb,     g_s,             512, b, n);
    else if (z == 1) s_body(g_x2u, g_u + 512,  g_sb + 1, g_s + HB*N_SP,   256, b, n);
    else             s_body(x3,    g_u + 1024, g_sb + 2, g_s + 2*HB*N_SP, 128, b, n);
}

// ---------------- q/k projection body (f32x2 tiled GEMM); q pre-scaled by log2e ------
template<int C, int D>
__device__ __forceinline__ void qkprep_body(
    float* __restrict__ smbuf,
    const float* __restrict__ X,
    const float* __restrict__ Wq, const float* __restrict__ bq,
    const float* __restrict__ Wk, const float* __restrict__ bk,
    float* __restrict__ qg, float* __restrict__ kg,
    int xb, int b)
{
    constexpr int ROWS = 2*D;          // 128 / 64 / 32
    constexpr int RGn  = ROWS/4;       // 32 / 16 / 8
    constexpr int NG   = 256/RGn;      // 8 / 16 / 32
    constexpr int BN   = NG*8;         // 64 / 128 / 256
    constexpr int WCG  = NG/8;         // 1 / 2 / 4
    constexpr int WDS  = 2*ROWS + 4;   // padded dup-w stride
    float* Xs = smbuf;                 // 16*BN
    float* Wd = smbuf + 16*BN;         // 16*WDS
    int tid = threadIdx.x;
    int lane = tid & 31, wid = tid >> 5;
    int cg = (lane & 7) + 8*(wid % WCG);
    int rg = (lane >> 3) + 4*(wid / WCG);
    int n0 = xb * BN;
    const float* Xb = X + (size_t)b * C * N_SP;

    ull acc[4][4];
    #pragma unroll
    for (int r = 0; r < 4; r++)
        #pragma unroll
        for (int p = 0; p < 4; p++) acc[r][p] = 0ull;

    for (int c0 = 0; c0 < C; c0 += 16){
        __syncthreads();
        #pragma unroll
        for (int i = 0; i < BN/16; i++){
            int idx = tid + i*256;
            int cc = idx / BN, n = idx % BN;
            Xs[cc*BN + n] = Xb[(size_t)(c0+cc)*N_SP + n0 + n];
        }
        #pragma unroll
        for (int i = 0; i < ROWS/16; i++){
            int idx = tid + i*256;
            int cc = idx & 15, r = idx >> 4;
            float w = (r < D) ? Wq[r*C + c0 + cc] : Wk[(r-D)*C + c0 + cc];
            *(float2*)&Wd[cc*WDS + 2*r] = make_float2(w, w);
        }
        __syncthreads();
        #pragma unroll
        for (int cc = 0; cc < 16; cc++){
            const ulonglong2* xp = (const ulonglong2*)(Xs + cc*BN + cg*8);
            ulonglong2 xa = xp[0], xb2 = xp[1];
            const ulonglong2* wp = (const ulonglong2*)(Wd + cc*WDS + rg*8);
            ulonglong2 wa = wp[0], wb = wp[1];
            ull xv0 = xa.x, xv1 = xa.y, xv2 = xb2.x, xv3 = xb2.y;
            ffma2(acc[0][0], wa.x, xv0); ffma2(acc[0][1], wa.x, xv1);
            ffma2(acc[0][2], wa.x, xv2); ffma2(acc[0][3], wa.x, xv3);
            ffma2(acc[1][0], wa.y, xv0); ffma2(acc[1][1], wa.y, xv1);
            ffma2(acc[1][2], wa.y, xv2); ffma2(acc[1][3], wa.y, xv3);
            ffma2(acc[2][0], wb.x, xv0); ffma2(acc[2][1], wb.x, xv1);
            ffma2(acc[2][2], wb.x, xv2); ffma2(acc[2][3], wb.x, xv3);
            ffma2(acc[3][0], wb.y, xv0); ffma2(acc[3][1], wb.y, xv1);
            ffma2(acc[3][2], wb.y, xv2); ffma2(acc[3][3], wb.y, xv3);
        }
    }
    #pragma unroll
    for (int r = 0; r < 4; r++){
        int row = rg*4 + r;
        #pragma unroll
        for (int p = 0; p < 4; p++){
            float lo, hi; unpack2(acc[r][p], lo, hi);
            int n = n0 + cg*8 + 2*p;
            if (row < D){
                float bqr = __ldg(&bq[row]);
                *(float2*)&qg[((size_t)b*D + row)*N_SP + n] =
                    make_float2((lo + bqr)*LOG2E, (hi + bqr)*LOG2E);
            } else {
                int rr = row - D;
                float bkr = __ldg(&bk[rr]);
                *(float2*)&kg[((size_t)b*D + rr)*N_SP + n] =
                    make_float2(lo + bkr, hi + bkr);
            }
        }
    }
}

// merged qkprep: grid (112, HB). x<64: scale0; x<96: scale1; else scale2.
__global__ __launch_bounds__(256) void qkprep_all(
    const float* __restrict__ x3,
    const float* __restrict__ Wq0, const float* __restrict__ bq0,
    const float* __restrict__ Wk0, const float* __restrict__ bk0,
    const float* __restrict__ Wq1, const float* __restrict__ bq1,
    const float* __restrict__ Wk1, const float* __restrict__ bk1,
    const float* __restrict__ Wq2, const float* __restrict__ bq2,
    const float* __restrict__ Wk2, const float* __restrict__ bk2)
{
    __shared__ __align__(16) float buf[5184];
    int x = blockIdx.x, b = blockIdx.y;
    if (x < 64)
        qkprep_body<512,64>(buf, g_x1u, Wq0, bq0, Wk0, bk0,
                            g_q + Q_OFF0, g_k + Q_OFF0, x, b);
    else if (x < 96)
        qkprep_body<256,32>(buf, g_x2u, Wq1, bq1, Wk1, bk1,
                            g_q + Q_OFF1, g_k + Q_OFF1, x - 64, b);
    else
        qkprep_body<128,16>(buf, x3, Wq2, bq2, Wk2, bk2,
                            g_q + Q_OFF2, g_k + Q_OFF2, x - 96, b);
}

// ---------------- barrier-free streaming attention (R13 structure + split epilogue) --
// a[n] = ba + sum_m 2^l[n,m] s[m] / sum_m 2^l[n,m]  (|l|<~90<127: no overflow).
// Per-warp DOUBLE-buffered k/s slices via cp.async, prefetch issued at tile top so
// the whole MMA+epilogue overlaps the load. No block barriers in the mainloop.
template<int D>
__device__ __forceinline__ void attn_body(
    const float* __restrict__ qg, const float* __restrict__ kg,
    const float* __restrict__ sg, const float* __restrict__ bap,
    float* __restrict__ aout, int nblk, int b)
{
    extern __shared__ float sm[];
    float* smq = sm;                    // D*64
    float* smk = sm + D*64;             // 8 warps * 2 bufs * D*16
    float* sms = sm + D*64 + 256*D;     // 8 * 2 * 16
    float* smr = sms + 256;             // 8*64*2
    int tid = threadIdx.x;
    int lane = tid & 31, w = tid >> 5;
    int n0 = nblk * 64;
    const float* qb = qg + (size_t)b * D * N_SP;
    const float* kb = kg + (size_t)b * D * N_SP;
    const float* sb = sg + (size_t)b * N_SP;

    #pragma unroll
    for (int i = 0; i < (D*64)/256; i++){
        int idx = tid + i*256;
        int kk = idx >> 6, n = idx & 63;
        smq[kk*64 + n] = qb[(size_t)kk*N_SP + n0 + n];
    }
    __syncthreads();

    float* myk = smk + w*(2*D*16);
    float* mys = sms + w*32;
    int m0 = w*16;                       // warp's m-offset within each 128-m tile
    int kko = lane >> 2, ch = (lane & 3)*4;

    // prefetch tile 0 -> buf 0 (per-warp)
    #pragma unroll
    for (int i = 0; i < D/8; i++){
        int kk = i*8 + kko;
        CPASYNC16(smaddr(&myk[kk*16 + ch]), &kb[(size_t)kk*N_SP + m0 + ch]);
    }
    if (lane < 4)
        CPASYNC16(smaddr(&mys[lane*4]), &sb[m0 + lane*4]);
    CPASYNC_COMMIT();
    CPASYNC_WAIT0();
    __syncwarp();

    float den0a = 0.f, den0b = 0.f, num0a = 0.f, num0b = 0.f;
    float den1a = 0.f, den1b = 0.f, num1a = 0.f, num1b = 0.f;

    for (int mt = 0; mt < 32; mt++){
        int cur = mt & 1;
        // issue next tile's loads into the other buffer (full-tile overlap)
        if (mt < 31){
            int nxt = cur ^ 1;
            int mg = (mt+1)*128 + m0;
            #pragma unroll
            for (int i = 0; i < D/8; i++){
                int kk = i*8 + kko;
                CPASYNC16(smaddr(&myk[nxt*D*16 + kk*16 + ch]),
                          &kb[(size_t)kk*N_SP + mg + ch]);
            }
            if (lane < 4)
                CPASYNC16(smaddr(&mys[nxt*16 + lane*4]), &sb[mg + lane*4]);
            CPASYNC_COMMIT();
        }
        const float* kbuf = myk + cur*D*16;

        ull acc[16];
        #pragma unroll
        for (int j = 0; j < 16; j++) acc[j] = 0ull;

        #pragma unroll 8
        for (int kk = 0; kk < D; kk++){
            ull qv = *(const ull*)&smq[kk*64 + 2*lane];
            float qlo, qhi; unpack2(qv, qlo, qhi);
            ull qx = dup2(qlo), qy = dup2(qhi);
            const ulonglong2* kr = (const ulonglong2*)(kbuf + kk*16);
            ulonglong2 k0 = kr[0], k1 = kr[1], k2 = kr[2], k3 = kr[3];
            ffma2(acc[0],  qx, k0.x); ffma2(acc[1],  qx, k0.y);
            ffma2(acc[2],  qx, k1.x); ffma2(acc[3],  qx, k1.y);
            ffma2(acc[4],  qx, k2.x); ffma2(acc[5],  qx, k2.y);
            ffma2(acc[6],  qx, k3.x); ffma2(acc[7],  qx, k3.y);
            ffma2(acc[8],  qy, k0.x); ffma2(acc[9],  qy, k0.y);
            ffma2(acc[10], qy, k1.x); ffma2(acc[11], qy, k1.y);
            ffma2(acc[12], qy, k2.x); ffma2(acc[13], qy, k2.y);
            ffma2(acc[14], qy, k3.x); ffma2(acc[15], qy, k3.y);
        }

        // split-accumulator inline epilogue; sv float4 shared between both rows
        #pragma unroll
        for (int jj = 0; jj < 4; jj++){
            float4 s4 = *(const float4*)&mys[cur*16 + 4*jj];
            float l0, l1, l2, l3;
            unpack2(acc[2*jj],   l0, l1);
            unpack2(acc[2*jj+1], l2, l3);
            float e0 = fexp2(l0), e1 = fexp2(l1), e2 = fexp2(l2), e3 = fexp2(l3);
            den0a += e0; den0b += e1;
            num0a = fmaf(e0, s4.x, num0a); num0b = fmaf(e1, s4.y, num0b);
            den0a += e2; den0b += e3;
            num0a = fmaf(e2, s4.z, num0a); num0b = fmaf(e3, s4.w, num0b);

            unpack2(acc[8+2*jj],   l0, l1);
            unpack2(acc[8+2*jj+1], l2, l3);
            e0 = fexp2(l0); e1 = fexp2(l1); e2 = fexp2(l2); e3 = fexp2(l3);
            den1a += e0; den1b += e1;
            num1a = fmaf(e0, s4.x, num1a); num1b = fmaf(e1, s4.y, num1b);
            den1a += e2; den1b += e3;
            num1a = fmaf(e2, s4.z, num1a); num1b = fmaf(e3, s4.w, num1b);
        }

        if (mt < 31){
            CPASYNC_WAIT0();
            __syncwarp();
        }
    }

    {
        int r0 = lane*2;
        float* p0 = &smr[(w*64 + r0)*2];
        p0[0] = den0a + den0b; p0[1] = num0a + num0b;
        float* p1 = &smr[(w*64 + r0 + 1)*2];
        p1[0] = den1a + den1b; p1[1] = num1a + num1b;
    }
    __syncthreads();
    if (tid < 64){
        float dsum = 0.f, nsum = 0.f;
        #pragma unroll
        for (int i = 0; i < 8; i++){
            dsum += smr[(i*64 + tid)*2];
            nsum += smr[(i*64 + tid)*2 + 1];
        }
        aout[(size_t)b*N_SP + n0 + tid] = bap[0] + nsum / dsum;
    }
}

// merged attention: grid.x = 768 (scale0 first for wave balance), 2 CTAs/SM
__global__ __launch_bounds__(256, 2) void attn_all(
    const float* __restrict__ ba0, const float* __restrict__ ba1,
    const float* __restrict__ ba2)
{
    int x = blockIdx.x;
    if (x < 256)
        attn_body<64>(g_q + Q_OFF0, g_k + Q_OFF0, g_s, ba0, g_a, x & 63, x >> 6);
    else if (x < 512){
        int y = x - 256;
        attn_body<32>(g_q + Q_OFF1, g_k + Q_OFF1, g_s + HB*N_SP, ba1,
                      g_a + HB*N_SP, y & 63, y >> 6);
    } else {
        int y = x - 512;
        attn_body<16>(g_q + Q_OFF2, g_k + Q_OFF2, g_s + 2*HB*N_SP, ba2,
                      g_a + 2*HB*N_SP, y & 63, y >> 6);
    }
}

// ---------------- final fused conv: out = w2 . relu(prod * (W1 . xcat) + b1) + b2 ----
__global__ __launch_bounds__(256) void final_kernel(
    const float* __restrict__ x3, const float* __restrict__ w1,
    const float* __restrict__ b1, const float* __restrict__ w2,
    const float* __restrict__ b2, float* __restrict__ out)
{
    __shared__ __align__(16) float Ws2[2][32*32];
    __shared__ float hred[128][33];
    int tid = threadIdx.x;
    int px = tid & 127, half = tid >> 7;
    int p = blockIdx.x * 128 + px;
    int b = p >> 12, n = p & 4095;

    ull tacc[16];
    #pragma unroll
    for (int j = 0; j < 16; j++) tacc[j] = 0ull;

    for (int i = 0; i < 14; i++){
        __syncthreads();
        #pragma unroll
        for (int k = 0; k < 4; k++){
            int idx = tid + k*256;
            int o = idx & 31, cc = idx >> 5;   // conflict-free STS
            Ws2[0][cc*32 + o] = w1[o*896 + i*32 + cc];
            Ws2[1][cc*32 + o] = w1[o*896 + 448 + i*32 + cc];
        }
        __syncthreads();
        int cbase = half*448 + i*32;
        const float* src; int cb;
        if (cbase < 128){ src = x3 + (size_t)b*128*N_SP; cb = cbase; }
        else if (cbase < 384){ src = g_x2u + (size_t)b*256*N_SP; cb = cbase - 128; }
        else { src = g_x1u + (size_t)b*512*N_SP; cb = cbase - 384; }
        const float* ws = Ws2[half];
        #pragma unroll 4
        for (int cc = 0; cc < 32; cc++){
            float x = src[(size_t)(cb+cc)*N_SP + n];
            ull xx = dup2(x);
            const ulonglong2* wp = (const ulonglong2*)(ws + cc*32);
            #pragma unroll
            for (int j = 0; j < 8; j++){
                ulonglong2 wv = wp[j];
                ffma2(tacc[2*j],   wv.x, xx);
                ffma2(tacc[2*j+1], wv.y, xx);
            }
        }
    }
    __syncthreads();
    if (half == 1){
        #pragma unroll
        for (int j = 0; j < 16; j++){
            float t0, t1; unpack2(tacc[j], t0, t1);
            hred[px][2*j] = t0; hred[px][2*j+1] = t1;
        }
    }
    __syncthreads();
    if (half == 0){
        float prod = g_a[p] * g_a[HB*N_SP + p] * g_a[2*HB*N_SP + p];
        float res = b2[0];
        #pragma unroll
        for (int j = 0; j < 16; j++){
            float t0, t1; unpack2(tacc[j], t0, t1);
            t0 += hred[px][2*j]; t1 += hred[px][2*j+1];
            int o = 2*j;
            res += w2[o]   * fmaxf(prod*t0 + b1[o],   0.f);
            res += w2[o+1] * fmaxf(prod*t1 + b1[o+1], 0.f);
        }
        out[p] = res;
    }
}

// ---------------- host launcher ----------------
// 5 launches. Our launch #4 = attn_all = global launch #6 (ncu capture target).
extern "C" void kernel_launch(void* const* d_in, const int* in_sizes, int n_in,
                              void* d_out, int out_size)
{
    const float* x3 = (const float*)d_in[0];
    const float* x2 = (const float*)d_in[1];
    const float* x1 = (const float*)d_in[2];

    // smem floats for attn: q D*64 + k 2*128*D (double) + s 256 + merge 1024
    // D=64 -> 87040 B -> 2 CTAs/SM
    const int SMEMA = (64*64 + 256*64 + 256 + 1024) * 4;
    cudaFuncSetAttribute(attn_all, cudaFuncAttributeMaxDynamicSharedMemorySize, SMEMA);

    // #1: pre (3x u + upsample x1 + upsample x2)
    pre_all<<<14 + (HB*512*N_SP)/256 + (HB*256*N_SP)/256, 256>>>(
        (const float*)d_in[9],  (const float*)d_in[7],  (const float*)d_in[8],
        (const float*)d_in[17], (const float*)d_in[15], (const float*)d_in[16],
        (const float*)d_in[25], (const float*)d_in[23], (const float*)d_in[24],
        x1, x2);

    // #2: merged s (3 scales)
    s_all<<<dim3(16, HB, 3), 256>>>(x3);

    // #3: merged q/k projections
    qkprep_all<<<dim3(112, HB), 256>>>(x3,
        (const float*)d_in[3],  (const float*)d_in[4],
        (const float*)d_in[5],  (const float*)d_in[6],
        (const float*)d_in[11], (const float*)d_in[12],
        (const float*)d_in[13], (const float*)d_in[14],
        (const float*)d_in[19], (const float*)d_in[20],
        (const float*)d_in[21], (const float*)d_in[22]);

    // #4: merged attention (capture target)
    attn_all<<<768, 256, SMEMA>>>((const float*)d_in[10], (const float*)d_in[18],
                                  (const float*)d_in[26]);

    // #5: fused final
    final_kernel<<<(HB*N_SP)/128, 256>>>(x3, (const float*)d_in[27], (const float*)d_in[28],
                                         (const float*)d_in[29], (const float*)d_in[30],
                                         (float*)d_out);
}